// round 14
// baseline (speedup 1.0000x reference)
#include <cuda_runtime.h>

// Depthwise 1D cross-correlation, 13-tap kernel shared across 16384 rows of L=4096 fp32.
// out[r,l] = sum_j kern[j]*x[r, l+j-6], zero-padded; kern[j] = w[6-j] (j<7) else w[j].
//
// R7: R6's shifted-window gather (4 aligned LDG.128 per quad, shuffle-realign,
// lane-0 self-fix), but with ALL loads for both quads front-batched before any
// FMA: MLP_p1 4 -> 10, hiding DRAM latency that R6 left exposed (all pipes <70%).

#define TAPS 13
#define LVAL 4096
#define THREADS 256

__global__ __launch_bounds__(THREADS)
void dwconv13_kernel(const float* __restrict__ x,
                     const float* __restrict__ w,
                     float* __restrict__ out)
{
    const unsigned FULL = 0xffffffffu;
    const int g    = blockIdx.x * THREADS + threadIdx.x;
    const int lane = threadIdx.x & 31;
    const long long rowBase = (long long)(g >> 9) * LVAL;   // 512 threads per row
    const int colA = (g & 511) * 4;                         // 0..2044
    const int colB = colA + 2048;                           // 2048..4092

    const float* pA = x + rowBase + colA;
    const float* pB = x + rowBase + colB;
    const float4 Z = make_float4(0.f, 0.f, 0.f, 0.f);

    // ---- FRONT-BATCHED LOADS (10 independent global loads in flight) ----
    // Quad A blocks: cols colA-4 .. colA+11 (left row-edge only at colA==0)
    float4 Am1 = (colA >= 4) ? *reinterpret_cast<const float4*>(pA - 4) : Z;
    float4 Am0 = *reinterpret_cast<const float4*>(pA);
    float4 Ap1 = *reinterpret_cast<const float4*>(pA + 4);
    float4 Ap2 = *reinterpret_cast<const float4*>(pA + 8);
    // Quad B blocks: cols colB-4 .. colB+11 (right row-edge at colB>=4088)
    float4 Bm1 = *reinterpret_cast<const float4*>(pB - 4);
    float4 Bm0 = *reinterpret_cast<const float4*>(pB);
    float4 Bp1 = (colB < LVAL - 4) ? *reinterpret_cast<const float4*>(pB + 4) : Z;
    float4 Bp2 = (colB < LVAL - 8) ? *reinterpret_cast<const float4*>(pB + 8) : Z;
    // Lane-0 halo pairs (cols col-6, col-5), front-batched too
    float2 Ah = make_float2(0.f, 0.f), Bh = make_float2(0.f, 0.f);
    if (lane == 0) {
        if (colA >= 8) Ah = *reinterpret_cast<const float2*>(pA - 6);
        Bh = *reinterpret_cast<const float2*>(pB - 6);      // colB-6 >= 2042 always ok
    }

    // Taps, flipped: kern[j] = w[6-j] (j<7), w[j] (j>=7)
    float4 w0 = *reinterpret_cast<const float4*>(w + 0);
    float4 w1 = *reinterpret_cast<const float4*>(w + 4);
    float4 w2 = *reinterpret_cast<const float4*>(w + 8);
    float  w12 = __ldg(w + 12);
    float kern[TAPS] = {w1.z, w1.y, w1.x, w0.w, w0.z, w0.y, w0.x,
                        w1.w, w2.x, w2.y, w2.z, w2.w, w12};

    // ---- QUAD A compute ----
    {
        float v[16] = {Am1.x, Am1.y, Am1.z, Am1.w, Am0.x, Am0.y, Am0.z, Am0.w,
                       Ap1.x, Ap1.y, Ap1.z, Ap1.w, Ap2.x, Ap2.y, Ap2.z, Ap2.w};
        float a0 = 0.f, a1 = 0.f, a2 = 0.f, a3 = 0.f;
        #pragma unroll
        for (int j = 0; j < TAPS; j++) {
            float kj = kern[j];
            a0 = fmaf(kj, v[j + 0], a0);
            a1 = fmaf(kj, v[j + 1], a1);
            a2 = fmaf(kj, v[j + 2], a2);
            a3 = fmaf(kj, v[j + 3], a3);
        }
        float e0 = 0.f, e1 = 0.f;
        if (lane == 0) {
            float u[14] = {Ah.x, Ah.y, Am1.x, Am1.y, Am1.z, Am1.w,
                           Am0.x, Am0.y, Am0.z, Am0.w, Ap1.x, Ap1.y, Ap1.z, Ap1.w};
            #pragma unroll
            for (int j = 0; j < TAPS; j++) {
                e0 = fmaf(kern[j], u[j + 0], e0);
                e1 = fmaf(kern[j], u[j + 1], e1);
            }
        }
        float sa = __shfl_up_sync(FULL, a2, 1);
        float sb = __shfl_up_sync(FULL, a3, 1);
        if (lane == 0) { sa = e0; sb = e1; }
        *reinterpret_cast<float4*>(out + rowBase + colA) = make_float4(sa, sb, a0, a1);
    }

    // ---- QUAD B compute ----
    {
        float v[16] = {Bm1.x, Bm1.y, Bm1.z, Bm1.w, Bm0.x, Bm0.y, Bm0.z, Bm0.w,
                       Bp1.x, Bp1.y, Bp1.z, Bp1.w, Bp2.x, Bp2.y, Bp2.z, Bp2.w};
        float a0 = 0.f, a1 = 0.f, a2 = 0.f, a3 = 0.f;
        #pragma unroll
        for (int j = 0; j < TAPS; j++) {
            float kj = kern[j];
            a0 = fmaf(kj, v[j + 0], a0);
            a1 = fmaf(kj, v[j + 1], a1);
            a2 = fmaf(kj, v[j + 2], a2);
            a3 = fmaf(kj, v[j + 3], a3);
        }
        float e0 = 0.f, e1 = 0.f;
        if (lane == 0) {
            float u[14] = {Bh.x, Bh.y, Bm1.x, Bm1.y, Bm1.z, Bm1.w,
                           Bm0.x, Bm0.y, Bm0.z, Bm0.w, Bp1.x, Bp1.y, Bp1.z, Bp1.w};
            #pragma unroll
            for (int j = 0; j < TAPS; j++) {
                e0 = fmaf(kern[j], u[j + 0], e0);
                e1 = fmaf(kern[j], u[j + 1], e1);
            }
        }
        float sa = __shfl_up_sync(FULL, a2, 1);
        float sb = __shfl_up_sync(FULL, a3, 1);
        if (lane == 0) { sa = e0; sb = e1; }
        *reinterpret_cast<float4*>(out + rowBase + colB) = make_float4(sa, sb, a0, a1);
    }
}

extern "C" void kernel_launch(void* const* d_in, const int* in_sizes, int n_in,
                              void* d_out, int out_size)
{
    const float* x = (const float*)d_in[0];
    const float* w = (const float*)d_in[1];
    float* out     = (float*)d_out;

    const int n = in_sizes[0];                 // 16384 * 4096
    const int nThreadsTotal = n / 8;           // 8 outputs per thread (2 quads)
    dwconv13_kernel<<<nThreadsTotal / THREADS, THREADS>>>(x, w, out);
}

// round 15
// speedup vs baseline: 1.0619x; 1.0619x over previous
#include <cuda_runtime.h>

// Depthwise 1D cross-correlation, 13-tap kernel shared across 16384 rows of L=4096 fp32.
// out[r,l] = sum_j kern[j]*x[r, l+j-6], zero-padded; kern[j] = w[6-j] (j<7) else w[j].
//
// R8: aligned-quad ownership. Thread owns out[col..col+3]; window col-6..col+9
// comes from its own 4 aligned LDG.128 (col-4..col+11) plus 2 floats from lane-1
// via shfl_up(1) (lane 0: one predicated LDG.64). Removes R6's branchy 26-FMA
// lane-0 recompute (~27% of issue) while keeping identical DRAM traffic.

#define TAPS 13
#define LVAL 4096
#define THREADS 256

template<bool EDGE_LEFT, bool EDGE_RIGHT>
__device__ __forceinline__ void do_quad(const float* __restrict__ x,
                                        float* __restrict__ out,
                                        long long rowBase, int col, int lane,
                                        const float kern[TAPS])
{
    const unsigned FULL = 0xffffffffu;
    const float* p = x + rowBase + col;
    const float4 Z = make_float4(0.f, 0.f, 0.f, 0.f);

    // Own blocks: cols col-4 .. col+11 (p2.z/.w unused)
    float4 m1 = (!EDGE_LEFT  || col >= 4)       ? *reinterpret_cast<const float4*>(p - 4) : Z;
    float4 m0 = *reinterpret_cast<const float4*>(p);
    float4 p1 = (!EDGE_RIGHT || col < LVAL - 4) ? *reinterpret_cast<const float4*>(p + 4) : Z;
    float4 p2 = (!EDGE_RIGHT || col < LVAL - 8) ? *reinterpret_cast<const float4*>(p + 8) : Z;

    // Cols col-6, col-5: lane-1's m1.z/m1.w. Lane 0: predicated 8B load
    // (lane 0 has col % 128 == 0, so col==0 (zeros) or col >= 128 (in-bounds)).
    float2 h = make_float2(0.f, 0.f);
    if (lane == 0 && (!EDGE_LEFT || col >= 8))
        h = *reinterpret_cast<const float2*>(p - 6);
    float w0 = __shfl_up_sync(FULL, m1.z, 1);
    float w1 = __shfl_up_sync(FULL, m1.w, 1);
    if (lane == 0) { w0 = h.x; w1 = h.y; }

    // v[t] = x[row, col-6+t], t = 0..15
    float v[16] = {w0,   w1,   m1.x, m1.y, m1.z, m1.w, m0.x, m0.y,
                   m0.z, m0.w, p1.x, p1.y, p1.z, p1.w, p2.x, p2.y};

    // out[col+k] = sum_j kern[j] * v[k+j]
    float a0 = 0.f, a1 = 0.f, a2 = 0.f, a3 = 0.f;
    #pragma unroll
    for (int j = 0; j < TAPS; j++) {
        float kj = kern[j];
        a0 = fmaf(kj, v[j + 0], a0);
        a1 = fmaf(kj, v[j + 1], a1);
        a2 = fmaf(kj, v[j + 2], a2);
        a3 = fmaf(kj, v[j + 3], a3);
    }

    *reinterpret_cast<float4*>(out + rowBase + col) = make_float4(a0, a1, a2, a3);
}

__global__ __launch_bounds__(THREADS)
void dwconv13_kernel(const float* __restrict__ x,
                     const float* __restrict__ w,
                     float* __restrict__ out)
{
    const int g    = blockIdx.x * THREADS + threadIdx.x;
    const int lane = threadIdx.x & 31;
    const long long rowBase = (long long)(g >> 9) * LVAL;   // 512 threads per row
    const int colA = (g & 511) * 4;                         // 0..2044 (warp = 128-col chunk)

    // Taps, flipped: kern[j] = w[6-j] (j<7), w[j] (j>=7)
    float4 w0 = *reinterpret_cast<const float4*>(w + 0);
    float4 w1 = *reinterpret_cast<const float4*>(w + 4);
    float4 w2 = *reinterpret_cast<const float4*>(w + 8);
    float  w12 = __ldg(w + 12);
    float kern[TAPS] = {w1.z, w1.y, w1.x, w0.w, w0.z, w0.y, w0.x,
                        w1.w, w2.x, w2.y, w2.z, w2.w, w12};

    // Quad A: cols 0..2047 (left row-edge possible), Quad B: cols 2048..4095 (right edge)
    do_quad<true, false>(x, out, rowBase, colA, lane, kern);
    do_quad<false, true>(x, out, rowBase, colA + 2048, lane, kern);
}

extern "C" void kernel_launch(void* const* d_in, const int* in_sizes, int n_in,
                              void* d_out, int out_size)
{
    const float* x = (const float*)d_in[0];
    const float* w = (const float*)d_in[1];
    float* out     = (float*)d_out;

    const int n = in_sizes[0];                 // 16384 * 4096
    const int nThreadsTotal = n / 8;           // 8 outputs per thread (2 quads)
    dwconv13_kernel<<<nThreadsTotal / THREADS, THREADS>>>(x, w, out);
}

// round 16
// speedup vs baseline: 1.1491x; 1.0821x over previous
#include <cuda_runtime.h>

// Depthwise 1D cross-correlation, 13-tap kernel shared across 16384 rows of L=4096 fp32.
// out[r,l] = sum_j kern[j]*x[r, l+j-6], zero-padded; kern[j] = w[6-j] (j<7) else w[j].
//
// R9: R8's aligned-quad gather, with taps moved to __constant__ memory.
// Warp-uniform LDCU promotes taps to uniform registers -> ~13 fewer per-thread
// regs; __launch_bounds__(256,8) forces 64-warp occupancy for latency hiding.

#define TAPS 13
#define LVAL 4096
#define THREADS 256

__constant__ float c_w[16];   // raw taps w[0..12] (unflipped)

template<bool EDGE_LEFT, bool EDGE_RIGHT>
__device__ __forceinline__ void do_quad(const float* __restrict__ x,
                                        float* __restrict__ out,
                                        long long rowBase, int col, int lane)
{
    const unsigned FULL = 0xffffffffu;
    const float* p = x + rowBase + col;
    const float4 Z = make_float4(0.f, 0.f, 0.f, 0.f);

    // Own blocks: cols col-4 .. col+11 (p2.z/.w unused)
    float4 m1 = (!EDGE_LEFT  || col >= 4)       ? *reinterpret_cast<const float4*>(p - 4) : Z;
    float4 m0 = *reinterpret_cast<const float4*>(p);
    float4 p1 = (!EDGE_RIGHT || col < LVAL - 4) ? *reinterpret_cast<const float4*>(p + 4) : Z;
    float4 p2 = (!EDGE_RIGHT || col < LVAL - 8) ? *reinterpret_cast<const float4*>(p + 8) : Z;

    // Cols col-6, col-5: lane-1's m1.z/m1.w. Lane 0: predicated 8B load.
    float2 h = make_float2(0.f, 0.f);
    if (lane == 0 && (!EDGE_LEFT || col >= 8))
        h = *reinterpret_cast<const float2*>(p - 6);
    float h0 = __shfl_up_sync(FULL, m1.z, 1);
    float h1 = __shfl_up_sync(FULL, m1.w, 1);
    if (lane == 0) { h0 = h.x; h1 = h.y; }

    // v[t] = x[row, col-6+t], t = 0..15
    float v[16] = {h0,   h1,   m1.x, m1.y, m1.z, m1.w, m0.x, m0.y,
                   m0.z, m0.w, p1.x, p1.y, p1.z, p1.w, p2.x, p2.y};

    // out[col+k] = sum_j kern[j] * v[k+j];  kern[j] = c_w[6-j] (j<7) else c_w[j].
    float a0 = 0.f, a1 = 0.f, a2 = 0.f, a3 = 0.f;
    #pragma unroll
    for (int j = 0; j < TAPS; j++) {
        const float kj = (j < 7) ? c_w[6 - j] : c_w[j];   // compile-time index, LDCU->UR
        a0 = fmaf(kj, v[j + 0], a0);
        a1 = fmaf(kj, v[j + 1], a1);
        a2 = fmaf(kj, v[j + 2], a2);
        a3 = fmaf(kj, v[j + 3], a3);
    }

    *reinterpret_cast<float4*>(out + rowBase + col) = make_float4(a0, a1, a2, a3);
}

__global__ __launch_bounds__(THREADS, 8)
void dwconv13_kernel(const float* __restrict__ x,
                     float* __restrict__ out)
{
    const int g    = blockIdx.x * THREADS + threadIdx.x;
    const int lane = threadIdx.x & 31;
    const long long rowBase = (long long)(g >> 9) * LVAL;   // 512 threads per row
    const int colA = (g & 511) * 4;                         // 0..2044 (warp = 128-col chunk)

    // Quad A: cols 0..2047 (left row-edge possible), Quad B: cols 2048..4095 (right edge)
    do_quad<true, false>(x, out, rowBase, colA, lane);
    do_quad<false, true>(x, out, rowBase, colA + 2048, lane);
}

extern "C" void kernel_launch(void* const* d_in, const int* in_sizes, int n_in,
                              void* d_out, int out_size)
{
    const float* x = (const float*)d_in[0];
    const float* w = (const float*)d_in[1];
    float* out     = (float*)d_out;

    // Taps into constant bank (graph-capturable async D2D memcpy node).
    cudaMemcpyToSymbolAsync(c_w, w, TAPS * sizeof(float), 0,
                            cudaMemcpyDeviceToDevice, 0);

    const int n = in_sizes[0];                 // 16384 * 4096
    const int nThreadsTotal = n / 8;           // 8 outputs per thread (2 quads)
    dwconv13_kernel<<<nThreadsTotal / THREADS, THREADS>>>(x, out);
}